// round 6
// baseline (speedup 1.0000x reference)
#include <cuda_runtime.h>
#include <cstdint>

#define MAXN 100000
#define MAXE 1600000
#define D    128
#define G    64
#define REP  32
#define SCB  1024
#define TM   64      // nodes per fused-kernel block
#define PAD  132     // At row pitch (floats): conflict-free for both STS.128 and mma LDS

// ---------------- device scratch ----------------
__device__ float g_h2[MAXN * D];        // layer-1 output (only intermediate)
__device__ int   g_deg[MAXN];
__device__ float g_dis[MAXN];
__device__ int   g_off[MAXN + 1];
__device__ int   g_cursor[MAXN];
__device__ int2  g_adj[MAXE];           // {src, bitcast(norm)}
__device__ float g_gsum[G * REP];
__device__ int   g_bsum[128];
__device__ int   g_bbase[128];
__device__ int   g_is64;
__device__ float g_Wf[2 * 16384];       // tf32 W1/W2 in mma fragment order

// ---------------- dtype-agnostic index read ----------------
__device__ __forceinline__ int idx_at(const void* p, size_t i) {
    if (g_is64) return (int)((const long long*)p)[i];
    return ((const int*)p)[i];
}

__device__ __forceinline__ uint32_t f2tf32(float x) {
    uint32_t u;
    asm("cvt.rna.tf32.f32 %0, %1;" : "=r"(u) : "f"(x));
    return u;
}

// ---------------- W prep: tf32-round + permute to m16n8k8 B-fragment order ----------------
// layout: Wf[layer][ ((ks*16 + ntile)*32 + lane)*2 + reg ]
//   b0 = W[ks*8 + tig    ][ntile*8 + g],  b1 = W[ks*8 + tig + 4][ntile*8 + g]
__global__ void k_wprep(const float* __restrict__ W1, const float* __restrict__ W2) {
    int i = blockIdx.x * blockDim.x + threadIdx.x;   // 0 .. 32767
    int l = i >> 14;
    int r = i & 16383;
    int reg = r & 1;
    int lane = (r >> 1) & 31;
    int ntile = (r >> 6) & 15;
    int ks = r >> 10;
    int gq = lane >> 2, tig = lane & 3;
    int k = ks * 8 + tig + reg * 4;
    int nn = ntile * 8 + gq;
    const float* W = l ? W2 : W1;
    g_Wf[l * 16384 + r] = __uint_as_float(f2tf32(W[k * D + nn]));
}

// ---------------- init (+dtype detect) ----------------
__global__ void k_init(const int* __restrict__ ei32, int n) {
    int i = blockIdx.x * blockDim.x + threadIdx.x;
    if (i == 0) {
        int allz = 1;
        for (int j = 1; j < 32; j += 2)
            if (ei32[j] != 0) allz = 0;
        g_is64 = allz;
    }
    if (i < n) { g_deg[i] = 1; g_cursor[i] = 0; }
    if (i < G * REP) g_gsum[i] = 0.f;
}

// ---------------- in-degree count ----------------
__global__ void k_deg(const void* __restrict__ ei, int e) {
    int i = blockIdx.x * blockDim.x + threadIdx.x;
    if (i < e) atomicAdd(&g_deg[idx_at(ei, (size_t)e + i)], 1);
}

// ---------------- scan phase 1: block sums of (deg-1); also dis=rsqrt(deg) ----------------
__global__ void k_scan1(int n) {
    int i = blockIdx.x * SCB + threadIdx.x;
    int v = 0;
    if (i < n) {
        int d = g_deg[i];
        g_dis[i] = rsqrtf((float)d);
        v = d - 1;
    }
    int s = v;
#pragma unroll
    for (int o = 16; o; o >>= 1) s += __shfl_down_sync(0xffffffffu, s, o);
    __shared__ int ws[SCB / 32];
    int w = threadIdx.x >> 5, l = threadIdx.x & 31;
    if (l == 0) ws[w] = s;
    __syncthreads();
    if (w == 0) {
        int t = (l < SCB / 32) ? ws[l] : 0;
#pragma unroll
        for (int o = 16; o; o >>= 1) t += __shfl_down_sync(0xffffffffu, t, o);
        if (l == 0) g_bsum[blockIdx.x] = t;
    }
}

// ---------------- scan phase 2 ----------------
__global__ void k_scan2(int nb, int n) {
    __shared__ int sm[128];
    int t = threadIdx.x;
    int v = (t < nb) ? g_bsum[t] : 0;
    sm[t] = v;
    __syncthreads();
    for (int o = 1; o < 128; o <<= 1) {
        int u = (t >= o) ? sm[t - o] : 0;
        __syncthreads();
        if (t >= o) sm[t] += u;
        __syncthreads();
    }
    g_bbase[t] = sm[t] - v;
    if (t == 127) g_off[n] = sm[127];
}

// ---------------- scan phase 3 ----------------
__global__ void k_scan3(int n) {
    int i = blockIdx.x * SCB + threadIdx.x;
    int v = (i < n) ? (g_deg[i] - 1) : 0;
    int incl = v;
#pragma unroll
    for (int o = 1; o < 32; o <<= 1) {
        int u = __shfl_up_sync(0xffffffffu, incl, o);
        if ((threadIdx.x & 31) >= o) incl += u;
    }
    __shared__ int ws[SCB / 32];
    int w = threadIdx.x >> 5, l = threadIdx.x & 31;
    if (l == 31) ws[w] = incl;
    __syncthreads();
    if (w == 0) {
        int s = (l < SCB / 32) ? ws[l] : 0;
        int si = s;
#pragma unroll
        for (int o = 1; o < 32; o <<= 1) {
            int u = __shfl_up_sync(0xffffffffu, si, o);
            if (l >= o) si += u;
        }
        ws[l] = si - s;
    }
    __syncthreads();
    if (i < n) g_off[i] = g_bbase[blockIdx.x] + ws[w] + (incl - v);
}

// ---------------- fill CSR ----------------
__global__ void k_fill(const void* __restrict__ ei, int e) {
    int i = blockIdx.x * blockDim.x + threadIdx.x;
    if (i < e) {
        int r = idx_at(ei, i);
        int c = idx_at(ei, (size_t)e + i);
        float w = g_dis[r] * g_dis[c];
        int pos = atomicAdd(&g_cursor[c], 1);
        g_adj[g_off[c] + pos] = make_int2(r, __float_as_int(w));
    }
}

// ---------------- fused layer: gather -> smem(tf32) -> tensor-core GEMM -> epilogue ----------------
__device__ __forceinline__ float leaky(float x) { return x >= 0.f ? x : 0.01f * x; }

template <int POOL>
__global__ __launch_bounds__(256, 3) void k_fused(
    const float4* __restrict__ in, const float* __restrict__ Wf,
    const float* __restrict__ bias, const float* __restrict__ fcW,
    const void* __restrict__ batch, float* __restrict__ hout, int n)
{
    __shared__ float At[TM][PAD];       // node-major agg tile, tf32-rounded
    __shared__ float rowsum[TM];

    int tid = threadIdx.x;
    int warp = tid >> 5, lane = tid & 31;
    int row0 = blockIdx.x * TM;

    // ---- phase 1: gather agg rows (warp per node, lane = feature quad) ----
    for (int nd = warp; nd < TM; nd += 8) {
        int node = row0 + nd;
        float4 acc = make_float4(0.f, 0.f, 0.f, 0.f);
        if (node < n) {
            float di = g_dis[node];
            float self = di * di;
            float4 v = in[(size_t)node * 32 + lane];
            acc.x = v.x * self; acc.y = v.y * self;
            acc.z = v.z * self; acc.w = v.w * self;
            int s = g_off[node], e = g_off[node + 1];
            int j = s;
            int2 a = make_int2(0, 0);
            if (j < e) a = g_adj[j];
            for (; j < e; j++) {
                int2 nx = a;
                if (j + 1 < e) nx = g_adj[j + 1];
                float w = __int_as_float(a.y);
                float4 hv = in[(size_t)a.x * 32 + lane];
                acc.x += hv.x * w; acc.y += hv.y * w;
                acc.z += hv.z * w; acc.w += hv.w * w;
                a = nx;
            }
        }
        float4 st;
        st.x = __uint_as_float(f2tf32(acc.x));
        st.y = __uint_as_float(f2tf32(acc.y));
        st.z = __uint_as_float(f2tf32(acc.z));
        st.w = __uint_as_float(f2tf32(acc.w));
        *(float4*)&At[nd][lane * 4] = st;
    }
    if (POOL && tid < TM) rowsum[tid] = 0.f;
    __syncthreads();

    // ---- phase 2: tensor-core GEMM C[64x128] = At @ W ----
    int gq = lane >> 2, tig = lane & 3;
    int m0 = (warp & 3) * 16;           // 16-row strip
    int nb = (warp >> 2) * 8;           // 8 n-tiles (64 cols)
    float c[8][4];
#pragma unroll
    for (int nt = 0; nt < 8; nt++)
#pragma unroll
        for (int j = 0; j < 4; j++) c[nt][j] = 0.f;

#pragma unroll 4
    for (int ks = 0; ks < 16; ks++) {
        int k0 = ks * 8;
        uint32_t a0 = __float_as_uint(At[m0 + gq][k0 + tig]);
        uint32_t a1 = __float_as_uint(At[m0 + gq + 8][k0 + tig]);
        uint32_t a2 = __float_as_uint(At[m0 + gq][k0 + tig + 4]);
        uint32_t a3 = __float_as_uint(At[m0 + gq + 8][k0 + tig + 4]);
#pragma unroll
        for (int nt = 0; nt < 8; nt++) {
            float2 bv = *(const float2*)&Wf[(size_t)(((ks * 16) + nb + nt) * 32 + lane) * 2];
            uint32_t b0 = __float_as_uint(bv.x);
            uint32_t b1 = __float_as_uint(bv.y);
            asm volatile(
                "mma.sync.aligned.m16n8k8.row.col.f32.tf32.tf32.f32 "
                "{%0,%1,%2,%3}, {%4,%5,%6,%7}, {%8,%9}, {%0,%1,%2,%3};"
                : "+f"(c[nt][0]), "+f"(c[nt][1]), "+f"(c[nt][2]), "+f"(c[nt][3])
                : "r"(a0), "r"(a1), "r"(a2), "r"(a3), "r"(b0), "r"(b1));
        }
    }

    // ---- phase 3: epilogue ----
    int r0 = row0 + m0 + gq;
    int r1 = r0 + 8;
    if (!POOL) {
#pragma unroll
        for (int nt = 0; nt < 8; nt++) {
            int col = (nb + nt) * 8 + tig * 2;
            float2 bb = *(const float2*)&bias[col];
            if (r0 < n) {
                float2 o = make_float2(leaky(c[nt][0] + bb.x), leaky(c[nt][1] + bb.y));
                *(float2*)&hout[(size_t)r0 * D + col] = o;
            }
            if (r1 < n) {
                float2 o = make_float2(leaky(c[nt][2] + bb.x), leaky(c[nt][3] + bb.y));
                *(float2*)&hout[(size_t)r1 * D + col] = o;
            }
        }
    } else {
        float p0 = 0.f, p1 = 0.f;
#pragma unroll
        for (int nt = 0; nt < 8; nt++) {
            int col = (nb + nt) * 8 + tig * 2;
            float2 bb = *(const float2*)&bias[col];
            float2 ff = *(const float2*)&fcW[col];
            p0 += leaky(c[nt][0] + bb.x) * ff.x + leaky(c[nt][1] + bb.y) * ff.y;
            p1 += leaky(c[nt][2] + bb.x) * ff.x + leaky(c[nt][3] + bb.y) * ff.y;
        }
        p0 += __shfl_xor_sync(0xffffffffu, p0, 1);
        p0 += __shfl_xor_sync(0xffffffffu, p0, 2);
        p1 += __shfl_xor_sync(0xffffffffu, p1, 1);
        p1 += __shfl_xor_sync(0xffffffffu, p1, 2);
        if (tig == 0) {
            atomicAdd(&rowsum[m0 + gq], p0);
            atomicAdd(&rowsum[m0 + gq + 8], p1);
        }
        __syncthreads();
        if (tid < TM) {
            int row = row0 + tid;
            if (row < n) {
                int g = idx_at(batch, row);
                atomicAdd(&g_gsum[g * REP + (blockIdx.x & (REP - 1))], rowsum[tid]);
            }
        }
    }
}

// ---------------- final: counts via binary search over sorted batch ----------------
__global__ void k_final(const void* __restrict__ batch, const float* __restrict__ fcb,
                        float* __restrict__ out, int n) {
    __shared__ int lb[G + 1];
    int t = threadIdx.x;
    if (t <= G) {
        int lo = 0, hi = n;
        while (lo < hi) {
            int mid = (lo + hi) >> 1;
            if (idx_at(batch, mid) < t) lo = mid + 1; else hi = mid;
        }
        lb[t] = lo;
    }
    __syncthreads();
    if (t < G) {
        float s = 0.f;
#pragma unroll
        for (int r = 0; r < REP; r++) s += g_gsum[t * REP + r];
        float c = (float)(lb[t + 1] - lb[t]);
        if (c < 1.f) c = 1.f;
        out[t] = s / c + fcb[0];
    }
}

// ---------------- launch ----------------
extern "C" void kernel_launch(void* const* d_in, const int* in_sizes, int n_in,
                              void* d_out, int out_size) {
    const float* x    = (const float*)d_in[0];
    const void*  ei   = d_in[1];
    const void*  bat  = d_in[2];
    const float* W1   = (const float*)d_in[3];
    const float* b1   = (const float*)d_in[4];
    const float* W2   = (const float*)d_in[5];
    const float* b2   = (const float*)d_in[6];
    const float* fcW  = (const float*)d_in[7];
    const float* fcb  = (const float*)d_in[8];
    float*       out  = (float*)d_out;

    int n = in_sizes[0] / D;
    int e = in_sizes[1] / 2;
    int nb = (n + SCB - 1) / SCB;

    float *h2, *wf;
    cudaGetSymbolAddress((void**)&h2, g_h2);
    cudaGetSymbolAddress((void**)&wf, g_Wf);

    int tb = 256;
    // W fragment prep (independent of CSR)
    k_wprep<<<128, 256>>>(W1, W2);
    // CSR build
    k_init<<<(n + tb - 1) / tb, tb>>>((const int*)ei, n);
    k_deg<<<(e + tb - 1) / tb, tb>>>(ei, e);
    k_scan1<<<nb, SCB>>>(n);
    k_scan2<<<1, 128>>>(nb, n);
    k_scan3<<<nb, SCB>>>(n);
    k_fill<<<(e + tb - 1) / tb, tb>>>(ei, e);

    int gblk = (n + TM - 1) / TM;
    // layer 1: h2 = leaky(agg(x)@W1 + b1)
    k_fused<0><<<gblk, 256>>>((const float4*)x, wf, b1, nullptr, nullptr, h2, n);
    // layer 2 fused with pooling/fc
    k_fused<1><<<gblk, 256>>>((const float4*)h2, wf + 16384, b2, fcW, bat, nullptr, n);

    k_final<<<1, 128>>>(bat, fcb, out, n);
}